// round 5
// baseline (speedup 1.0000x reference)
#include <cuda_runtime.h>

// InnerProduct_541165879452 on GB300 (sm_103a)
// lp[r,p] = sum_f w[p,f]^2 * sum_e x[r,f,e]^2
// R=32768, F=64, E=16, P=10.  HBM-bound: stream 134 MB of x exactly once.

constexpr int R_DIM = 32768;
constexpr int F_DIM = 64;
constexpr int E_DIM = 16;
constexpr int P_DIM = 10;

constexpr int THREADS        = 256;
constexpr int ROWS_PER_BLOCK = 64;
constexpr int FLOATS_PER_ROW = F_DIM * E_DIM;          // 1024
constexpr int F4_PER_ROW     = FLOATS_PER_ROW / 4;     // 256
constexpr int XSQ_STRIDE     = F_DIM + 4;              // 68 floats = 272 B, 16B-aligned

__global__ __launch_bounds__(THREADS)
void InnerProduct_541165879452_kernel(const float4* __restrict__ x4,
                                      const float*  __restrict__ w,
                                      float*        __restrict__ out)
{
    __shared__ float xsq[ROWS_PER_BLOCK * XSQ_STRIDE];
    __shared__ float wsq[P_DIM * F_DIM];               // 640 floats

    const int tid = threadIdx.x;
    const long long rowbase = (long long)blockIdx.x * ROWS_PER_BLOCK;
    const float4* xb = x4 + rowbase * F4_PER_ROW;

    // w^2 into smem (L2-hit after first block; no sync needed until phase B)
    for (int j = tid; j < P_DIM * F_DIM; j += THREADS) {
        float v = w[j];
        wsq[j] = v * v;
    }

    // ---- Phase A: per-(r,f) sum of squares over e -> smem -------------------
    // Block-linear float4 loads: fully coalesced. Each float4 is within one f
    // (E=16 -> 4 float4 per f); lanes 4k..4k+3 share the same (r,f), reduce
    // with 2 shfl_down, lane 4k writes conflict-free STS.
    constexpr int ITERS = ROWS_PER_BLOCK * F4_PER_ROW / THREADS;   // 64
    #pragma unroll 8
    for (int i = 0; i < ITERS; i++) {
        int idx = i * THREADS + tid;
        float4 v = xb[idx];
        float s = v.x * v.x + v.y * v.y + v.z * v.z + v.w * v.w;
        s += __shfl_down_sync(0xffffffffu, s, 2);
        s += __shfl_down_sync(0xffffffffu, s, 1);
        if ((tid & 3) == 0) {
            int r = idx >> 8;                 // idx / F4_PER_ROW
            int f = (idx >> 2) & (F_DIM - 1); // (idx%256)/4
            xsq[r * XSQ_STRIDE + f] = s;
        }
    }
    __syncthreads();

    // ---- Phase B: 64x10 outputs, each a 64-wide dot from smem ---------------
    for (int o = tid; o < ROWS_PER_BLOCK * P_DIM; o += THREADS) {
        int r = o / P_DIM;
        int p = o - r * P_DIM;
        const float4* xr = reinterpret_cast<const float4*>(xsq + r * XSQ_STRIDE);
        const float4* wr = reinterpret_cast<const float4*>(wsq + p * F_DIM);
        float acc = 0.f;
        #pragma unroll
        for (int fc = 0; fc < F_DIM / 4; fc++) {
            float4 a = xr[fc];
            float4 b = wr[fc];
            acc += a.x * b.x + a.y * b.y + a.z * b.z + a.w * b.w;
        }
        out[rowbase * P_DIM + o] = acc;       // coalesced: o is the linear offset
    }
}

extern "C" void kernel_launch(void* const* d_in, const int* in_sizes, int n_in,
                              void* d_out, int out_size)
{
    const float4* x4 = (const float4*)d_in[0];   // x: [R, F, E] fp32, 134 MB
    const float*  w  = (const float*) d_in[1];   // weights: [P, F] fp32
    float* out = (float*)d_out;                  // [R, P] fp32

    (void)in_sizes; (void)n_in; (void)out_size;

    const int grid = R_DIM / ROWS_PER_BLOCK;     // 512 blocks
    InnerProduct_541165879452_kernel<<<grid, THREADS>>>(x4, w, out);
}

// round 7
// speedup vs baseline: 1.4521x; 1.4521x over previous
#include <cuda_runtime.h>

// InnerProduct_541165879452 on GB300 (sm_103a)
// lp[r,p] = sum_f w[p,f]^2 * sum_e x[r,f,e]^2
// R=32768, F=64, E=16, P=10.  Pure HBM stream: 134 MB of x read once.
//
// R5 lesson: the fused load->shfl->predicated-STS loop serialized to MLP=1
// (regs=38, DRAM 28.5%). Stage 8 independent coalesced LDG.128 into a
// register array FIRST, then reduce. Keeps block-linear (fully coalesced,
// 4 lines/LDG) global pattern for max L1 wavefront efficiency.

constexpr int R_DIM = 32768;
constexpr int F_DIM = 64;
constexpr int P_DIM = 10;

constexpr int THREADS        = 256;
constexpr int ROWS_PER_BLOCK = 16;
constexpr int F4_PER_ROW     = 256;                      // F*E/4
constexpr int XSQ_STRIDE     = F_DIM + 4;                // 68 floats, 16B-aligned rows
constexpr int ITERS          = ROWS_PER_BLOCK * F4_PER_ROW / THREADS;  // 16
constexpr int BATCH          = 8;                        // staged loads per batch
constexpr int NBATCH         = ITERS / BATCH;            // 2

__global__ __launch_bounds__(THREADS)
void InnerProduct_541165879452_kernel(const float4* __restrict__ x4,
                                      const float*  __restrict__ w,
                                      float*        __restrict__ out)
{
    __shared__ float xsq[ROWS_PER_BLOCK * XSQ_STRIDE];   // 4352 B
    __shared__ float wsq[P_DIM * F_DIM];                 // 2560 B

    const int tid = threadIdx.x;
    const long long rowbase = (long long)blockIdx.x * ROWS_PER_BLOCK;
    const float4* xb = x4 + rowbase * F4_PER_ROW;

    // w^2 into smem (tiny, L2-hit after first wave)
    for (int j = tid; j < P_DIM * F_DIM; j += THREADS) {
        float v = w[j];
        wsq[j] = v * v;
    }

    // ---- Phase A: per-(r,f) sum of squares over e -> smem -------------------
    // Each batch: 8 INDEPENDENT block-linear LDG.128 staged into registers
    // (front-batched => MLP>=8 per thread), then the shfl 4:1 e-reduction and
    // one predicated conflict-free STS per group of 4 lanes.
    #pragma unroll
    for (int b = 0; b < NBATCH; b++) {
        float4 v[BATCH];
        #pragma unroll
        for (int k = 0; k < BATCH; k++) {
            v[k] = xb[(b * BATCH + k) * THREADS + tid];
        }
        #pragma unroll
        for (int k = 0; k < BATCH; k++) {
            float s = v[k].x * v[k].x + v[k].y * v[k].y
                    + v[k].z * v[k].z + v[k].w * v[k].w;
            s += __shfl_down_sync(0xffffffffu, s, 2);
            s += __shfl_down_sync(0xffffffffu, s, 1);
            if ((tid & 3) == 0) {
                int idx = (b * BATCH + k) * THREADS + tid;
                int r = idx >> 8;                  // idx / F4_PER_ROW
                int f = (idx >> 2) & (F_DIM - 1);  // (idx % 256) / 4
                xsq[r * XSQ_STRIDE + f] = s;
            }
        }
    }
    __syncthreads();

    // ---- Phase B: 16x10 outputs, each a 64-wide dot from smem ---------------
    for (int o = tid; o < ROWS_PER_BLOCK * P_DIM; o += THREADS) {
        int r = o / P_DIM;
        int p = o - r * P_DIM;
        const float4* xr = reinterpret_cast<const float4*>(xsq + r * XSQ_STRIDE);
        const float4* wr = reinterpret_cast<const float4*>(wsq + p * F_DIM);
        float acc = 0.f;
        #pragma unroll
        for (int fc = 0; fc < F_DIM / 4; fc++) {
            float4 a = xr[fc];
            float4 bq = wr[fc];
            acc += a.x * bq.x + a.y * bq.y + a.z * bq.z + a.w * bq.w;
        }
        out[rowbase * P_DIM + o] = acc;            // contiguous 160-float store
    }
}

extern "C" void kernel_launch(void* const* d_in, const int* in_sizes, int n_in,
                              void* d_out, int out_size)
{
    const float4* x4 = (const float4*)d_in[0];   // x: [R, F, E] fp32
    const float*  w  = (const float*) d_in[1];   // weights: [P, F] fp32
    float* out = (float*)d_out;                  // [R, P] fp32

    (void)in_sizes; (void)n_in; (void)out_size;

    const int grid = R_DIM / ROWS_PER_BLOCK;     // 2048 blocks
    InnerProduct_541165879452_kernel<<<grid, THREADS>>>(x4, w, out);
}

// round 8
// speedup vs baseline: 2.1978x; 1.5135x over previous
#include <cuda_runtime.h>

// InnerProduct_541165879452 on GB300 (sm_103a)
// lp[r,p] = sum_f w[p,f]^2 * sum_e x[r,f,e]^2 ; R=32768, F=64, E=16, P=10.
//
// R7 lesson: kernel was l1tex-WAVEFRONT bound (L1=60% > DRAM=42%): STS +
// bank-conflicted phase-B LDS tripled l1tex traffic over the LDG minimum.
// This version keeps ONLY the LDG wavefronts: warp-per-row streaming, weights
// squared into per-lane registers, e-reduction + f-reduction via shfl_xor,
// accumulators in registers, predicated scalar stores. Zero shared memory.
//
// Mapping: row = 1024 floats = 256 float4. Batch k (k=0..7): lane L reads
// float4 g = 32k+L (contiguous 512B per warp, perfectly coalesced).
// f(g) = g>>2 = 8k + (L>>2).  j = L>>2 selects f within the batch,
// c = L&3 selects the e-quarter. After shfl_xor(1,2) every lane of a
// quarter-warp holds xsq[r][8k+j]. Lane (j,c) accumulates p = c+4i (i=0..2)
// with register weights wreg[k][i] = w[p][8k+j]^2 (0-padded for p>=10).
// f-reduction = shfl_xor over lane bits 2..4 (strides 4,8,16).

constexpr int R_DIM = 32768;
constexpr int F_DIM = 64;
constexpr int P_DIM = 10;

constexpr int THREADS       = 256;
constexpr int WARPS         = THREADS / 32;
constexpr int ROWS_PER_WARP = 4;
constexpr int F4_PER_ROW    = 256;          // F*E/4
constexpr int NP            = 3;            // p-slots per lane (c, c+4, c+8)

__global__ __launch_bounds__(THREADS)
void InnerProduct_541165879452_kernel(const float4* __restrict__ x4,
                                      const float*  __restrict__ w,
                                      float*        __restrict__ out)
{
    const int tid  = threadIdx.x;
    const int wid  = tid >> 5;
    const int lane = tid & 31;
    const int j    = lane >> 2;   // f-slot within batch
    const int c    = lane & 3;    // e-quarter / p-group

    // One-time: squared weights into registers, fixed for all rows this
    // warp will ever process. 24 scalar LDGs from a 2.5 KB tensor (L2-hot).
    float wreg[8][NP];
    #pragma unroll
    for (int k = 0; k < 8; k++) {
        #pragma unroll
        for (int i = 0; i < NP; i++) {
            int p = c + 4 * i;
            int f = 8 * k + j;
            float v = (p < P_DIM) ? w[p * F_DIM + f] : 0.0f;
            wreg[k][i] = v * v;
        }
    }

    const int warp_row0 = (blockIdx.x * WARPS + wid) * ROWS_PER_WARP;

    #pragma unroll
    for (int m = 0; m < ROWS_PER_WARP; m++) {
        const long long r = warp_row0 + m;
        const float4* xr = x4 + r * (long long)F4_PER_ROW;

        // Stage 8 independent coalesced LDG.128 (MLP=8, 4KB per warp-row).
        float4 v[8];
        #pragma unroll
        for (int k = 0; k < 8; k++)
            v[k] = xr[k * 32 + lane];

        float acc[NP] = {0.0f, 0.0f, 0.0f};

        #pragma unroll
        for (int k = 0; k < 8; k++) {
            float s = v[k].x * v[k].x + v[k].y * v[k].y
                    + v[k].z * v[k].z + v[k].w * v[k].w;
            // e-reduction across the quarter-warp: all 4 lanes get xsq[r][f]
            s += __shfl_xor_sync(0xffffffffu, s, 1);
            s += __shfl_xor_sync(0xffffffffu, s, 2);
            #pragma unroll
            for (int i = 0; i < NP; i++)
                acc[i] += wreg[k][i] * s;
        }

        // f-reduction: sum over j (lane bits 2..4)
        #pragma unroll
        for (int i = 0; i < NP; i++) {
            acc[i] += __shfl_xor_sync(0xffffffffu, acc[i], 4);
            acc[i] += __shfl_xor_sync(0xffffffffu, acc[i], 8);
            acc[i] += __shfl_xor_sync(0xffffffffu, acc[i], 16);
        }

        // lanes 0..3 (j=0) hold the final sums for p = c + 4i
        if (lane < 4) {
            #pragma unroll
            for (int i = 0; i < NP; i++) {
                int p = c + 4 * i;
                if (p < P_DIM)
                    out[r * P_DIM + p] = acc[i];
            }
        }
    }
}

extern "C" void kernel_launch(void* const* d_in, const int* in_sizes, int n_in,
                              void* d_out, int out_size)
{
    const float4* x4 = (const float4*)d_in[0];   // x: [R, F, E] fp32
    const float*  w  = (const float*) d_in[1];   // weights: [P, F] fp32
    float* out = (float*)d_out;                  // [R, P] fp32

    (void)in_sizes; (void)n_in; (void)out_size;

    const int grid = R_DIM / (WARPS * ROWS_PER_WARP);  // 1024 blocks
    InnerProduct_541165879452_kernel<<<grid, THREADS>>>(x4, w, out);
}

// round 10
// speedup vs baseline: 2.3453x; 1.0671x over previous
#include <cuda_runtime.h>

// InnerProduct_541165879452 on GB300 (sm_103a)
// lp[r,p] = sum_f w[p,f]^2 * sum_e x[r,f,e]^2 ; R=32768, F=64, E=16, P=10.
//
// R8 lesson: warp-per-row + register reduction got DRAM to 65%, limited by
// load-issue duty cycle (no bytes in flight during each row's ~200-cycle
// shfl/FMA phase; regs=56 proved ptxas kept a single load buffer).
// R9: explicit register double-buffer — prefetch row r+stride while
// computing row r — plus grid-stride persistent warps (304 blocks = 2/SM)
// to remove wave quantization. Every warp keeps ~4KB outstanding always.

constexpr int R_DIM = 32768;
constexpr int F_DIM = 64;
constexpr int P_DIM = 10;

constexpr int THREADS     = 256;
constexpr int WARPS       = THREADS / 32;
constexpr int BLOCKS      = 304;              // 2 per SM x 152 SMs
constexpr int TOTAL_WARPS = BLOCKS * WARPS;   // 2432
constexpr int F4_PER_ROW  = 256;              // F*E/4
constexpr int NP          = 3;                // p-slots per lane (c, c+4, c+8)

__global__ __launch_bounds__(THREADS, 2)
void InnerProduct_541165879452_kernel(const float4* __restrict__ x4,
                                      const float*  __restrict__ w,
                                      float*        __restrict__ out)
{
    const int tid  = threadIdx.x;
    const int wid  = tid >> 5;
    const int lane = tid & 31;
    const int j    = lane >> 2;   // f-slot within batch
    const int c    = lane & 3;    // e-quarter / p-group

    // Squared weights in registers, reused for every row this warp touches.
    float wreg[8][NP];
    #pragma unroll
    for (int k = 0; k < 8; k++) {
        #pragma unroll
        for (int i = 0; i < NP; i++) {
            int p = c + 4 * i;
            float v = (p < P_DIM) ? w[p * F_DIM + (8 * k + j)] : 0.0f;
            wreg[k][i] = v * v;
        }
    }

    const int warp_gid = blockIdx.x * WARPS + wid;

    // Per-row compute from a staged register buffer; writes out[r*P + p].
    auto compute_row = [&](const float4 (&v)[8], long long r) {
        float acc[NP] = {0.0f, 0.0f, 0.0f};
        #pragma unroll
        for (int k = 0; k < 8; k++) {
            float s = v[k].x * v[k].x + v[k].y * v[k].y
                    + v[k].z * v[k].z + v[k].w * v[k].w;
            // e-reduction across the quarter-warp (same f, 4 e-quarters)
            s += __shfl_xor_sync(0xffffffffu, s, 1);
            s += __shfl_xor_sync(0xffffffffu, s, 2);
            #pragma unroll
            for (int i = 0; i < NP; i++)
                acc[i] += wreg[k][i] * s;
        }
        // f-reduction over j (lane bits 2..4)
        #pragma unroll
        for (int i = 0; i < NP; i++) {
            acc[i] += __shfl_xor_sync(0xffffffffu, acc[i], 4);
            acc[i] += __shfl_xor_sync(0xffffffffu, acc[i], 8);
            acc[i] += __shfl_xor_sync(0xffffffffu, acc[i], 16);
        }
        if (lane < 4) {
            #pragma unroll
            for (int i = 0; i < NP; i++) {
                int p = c + 4 * i;
                if (p < P_DIM)
                    out[r * P_DIM + p] = acc[i];
            }
        }
    };

    // Clamped prefetch of a full row into a register buffer (8 x LDG.128).
    auto prefetch = [&](float4 (&v)[8], long long r) {
        long long rc = (r < R_DIM) ? r : (R_DIM - 1);   // clamp: harmless reload
        const float4* xr = x4 + rc * (long long)F4_PER_ROW;
        #pragma unroll
        for (int k = 0; k < 8; k++)
            v[k] = xr[k * 32 + lane];
    };

    float4 va[8], vb[8];
    long long r = warp_gid;
    if (r >= R_DIM) return;

    prefetch(va, r);

    // Ping-pong pipeline: loads for the next row are issued before the
    // current row's shfl/FMA phase, so ~4KB stays in flight per warp.
    while (true) {
        long long rn = r + TOTAL_WARPS;
        prefetch(vb, rn);
        compute_row(va, r);
        r = rn;
        if (r >= R_DIM) break;

        long long rnn = r + TOTAL_WARPS;
        prefetch(va, rnn);
        compute_row(vb, r);
        r = rnn;
        if (r >= R_DIM) break;
    }
}

extern "C" void kernel_launch(void* const* d_in, const int* in_sizes, int n_in,
                              void* d_out, int out_size)
{
    const float4* x4 = (const float4*)d_in[0];   // x: [R, F, E] fp32
    const float*  w  = (const float*) d_in[1];   // weights: [P, F] fp32
    float* out = (float*)d_out;                  // [R, P] fp32

    (void)in_sizes; (void)n_in; (void)out_size;

    InnerProduct_541165879452_kernel<<<BLOCKS, THREADS>>>(x4, w, out);
}